// round 1
// baseline (speedup 1.0000x reference)
#include <cuda_runtime.h>
#include <cuda_bf16.h>

// BFP quant-dequant: shared 8-bit exponent per block of 8 along the last dim.
// x: [8192, 12284] fp32 -> out same shape.
// Per row: 1535 full blocks of 8, plus a 4-element tail block (pad is zeros,
// which never changes maxabs, so we just process 4 real elements).

#define COLS 12284
#define BLOCKS_PER_ROW 1536      // ceil(12284/8)
#define FULL_BLOCKS 1535

__device__ __forceinline__ float qdq(float v, float recip, float step) {
    float q = rintf(v * recip);            // round-half-to-even, matches jnp.round
    q = fminf(fmaxf(q, -128.0f), 127.0f);  // clip to [-2^7, 2^7-1]
    return q * step;
}

__global__ __launch_bounds__(256) void bfp_quant_kernel(
    const float* __restrict__ x, float* __restrict__ out)
{
    const int b = blockIdx.x * 256 + threadIdx.x;   // block index within row, 0..1535
    const long long row = blockIdx.y;
    const long long base = row * (long long)COLS + (long long)b * 8;

    const bool full = (b < FULL_BLOCKS);

    const float4* __restrict__ src = reinterpret_cast<const float4*>(x + base);
    float4 a = src[0];
    float4 c;
    if (full) {
        c = src[1];
    } else {
        c.x = c.y = c.z = c.w = 0.0f;
    }

    // maxabs over the block
    float m = fmaxf(fmaxf(fabsf(a.x), fabsf(a.y)), fmaxf(fabsf(a.z), fabsf(a.w)));
    m = fmaxf(m, fmaxf(fmaxf(fabsf(c.x), fabsf(c.y)), fmaxf(fabsf(c.z), fabsf(c.w))));

    // maxabs = frac * 2^e, frac in [0.5, 1). step = 2^(e - (MBITS-1)) = 2^(e-7).
    // frexpf(0) -> e = 0, step = 2^-7, q = 0: all-zero block comes out zero. Exact.
    int e;
    frexpf(m, &e);
    const float step  = ldexpf(1.0f, e - 7);   // exact power of two
    const float recip = ldexpf(1.0f, 7 - e);   // exact reciprocal

    float4 oa, oc;
    oa.x = qdq(a.x, recip, step);
    oa.y = qdq(a.y, recip, step);
    oa.z = qdq(a.z, recip, step);
    oa.w = qdq(a.w, recip, step);

    float4* __restrict__ dst = reinterpret_cast<float4*>(out + base);
    dst[0] = oa;
    if (full) {
        oc.x = qdq(c.x, recip, step);
        oc.y = qdq(c.y, recip, step);
        oc.z = qdq(c.z, recip, step);
        oc.w = qdq(c.w, recip, step);
        dst[1] = oc;
    }
}

extern "C" void kernel_launch(void* const* d_in, const int* in_sizes, int n_in,
                              void* d_out, int out_size) {
    const float* x = (const float*)d_in[0];
    float* out = (float*)d_out;
    const int nrows = in_sizes[0] / COLS;     // 8192 for the reference shape

    dim3 grid(BLOCKS_PER_ROW / 256, nrows);   // (6, 8192), exact cover: 6*256 == 1536
    bfp_quant_kernel<<<grid, 256>>>(x, out);
}